// round 15
// baseline (speedup 1.0000x reference)
#include <cuda_runtime.h>
#include <cuda_bf16.h>
#include <cstdint>

// Problem constants
#define D_MODEL 512
#define S_LEN   2048
#define NB      2
#define NH      8
#define DK      64
#define MROWS   (NB * S_LEN)    // 4096
#define BHCNT   (NB * NH)       // 16
#define PAIRS   (DK / 2)        // 32 u32 per head row
#define DPAIRS  (D_MODEL / 2)   // 256 u32 per full row

// --------------------------------------------------------------------------
// Pre-split bf16 hi/lo planes (pair-packed u32 = [bf16 even | bf16 odd])
// --------------------------------------------------------------------------
__device__ uint32_t g_XAh[3][MROWS * DPAIRS];   // q/k/v activations
__device__ uint32_t g_XAl[3][MROWS * DPAIRS];
__device__ uint32_t g_Wh[4][D_MODEL * DPAIRS];  // w_q w_k w_v w_o
__device__ uint32_t g_Wl[4][D_MODEL * DPAIRS];
__device__ uint32_t g_Oh[MROWS * DPAIRS];       // attention output planes
__device__ uint32_t g_Ol[MROWS * DPAIRS];
// head-split projection outputs
__device__ uint32_t g_Qh[BHCNT * S_LEN * PAIRS];
__device__ uint32_t g_Ql[BHCNT * S_LEN * PAIRS];
__device__ uint32_t g_Kh[BHCNT * S_LEN * PAIRS];
__device__ uint32_t g_Kl[BHCNT * S_LEN * PAIRS];
__device__ uint32_t g_Vh[BHCNT * S_LEN * PAIRS];
__device__ uint32_t g_Vl[BHCNT * S_LEN * PAIRS];

// ===========================================================================
// Helpers (plain sm_75/80 PTX, no 'a'-features)
// ===========================================================================
__device__ __forceinline__ void mma_bf16(float* d, const uint32_t* a, const uint32_t* b)
{
    asm volatile(
        "mma.sync.aligned.m16n8k16.row.col.f32.bf16.bf16.f32 "
        "{%0,%1,%2,%3}, {%4,%5,%6,%7}, {%8,%9}, {%0,%1,%2,%3};"
        : "+f"(d[0]), "+f"(d[1]), "+f"(d[2]), "+f"(d[3])
        : "r"(a[0]), "r"(a[1]), "r"(a[2]), "r"(a[3]), "r"(b[0]), "r"(b[1]));
}

__device__ __forceinline__ void ldsm_x4(uint32_t* r, uint32_t addr)
{
    asm volatile("ldmatrix.sync.aligned.m8n8.x4.shared.b16 {%0,%1,%2,%3}, [%4];"
                 : "=r"(r[0]), "=r"(r[1]), "=r"(r[2]), "=r"(r[3]) : "r"(addr));
}
__device__ __forceinline__ void ldsm_x4_trans(uint32_t* r, uint32_t addr)
{
    asm volatile("ldmatrix.sync.aligned.m8n8.x4.trans.shared.b16 {%0,%1,%2,%3}, [%4];"
                 : "=r"(r[0]), "=r"(r[1]), "=r"(r[2]), "=r"(r[3]) : "r"(addr));
}

__device__ __forceinline__ uint32_t smem_u32(const void* p) {
    uint32_t addr;
    asm("{ .reg .u64 tmp; cvta.to.shared.u64 tmp, %1; cvt.u32.u64 %0, tmp; }"
        : "=r"(addr) : "l"(p));
    return addr;
}

__device__ __forceinline__ void cp_async16(uint32_t dst, const void* src) {
    asm volatile("cp.async.cg.shared.global [%0], [%1], 16;" :: "r"(dst), "l"(src));
}
__device__ __forceinline__ void cp_commit() {
    asm volatile("cp.async.commit_group;" ::: "memory");
}
template <int N>
__device__ __forceinline__ void cp_wait() {
    asm volatile("cp.async.wait_group %0;" :: "n"(N) : "memory");
}

__device__ __forceinline__ void split_bf16x2(float x, float y, uint32_t& h, uint32_t& l)
{
    __nv_bfloat162 hb = __floats2bfloat162_rn(x, y);
    h = *reinterpret_cast<uint32_t*>(&hb);
    float rx = x - __bfloat162float(hb.x);
    float ry = y - __bfloat162float(hb.y);
    __nv_bfloat162 lb = __floats2bfloat162_rn(rx, ry);
    l = *reinterpret_cast<uint32_t*>(&lb);
}

// ===========================================================================
// Pre-split pass: fp32 -> bf16 hi/lo planes. One pair per thread.
// ===========================================================================
__global__ __launch_bounds__(256) void split_inputs(
    const float* __restrict__ q, const float* __restrict__ k,
    const float* __restrict__ v,
    const float* __restrict__ wq, const float* __restrict__ wk,
    const float* __restrict__ wv, const float* __restrict__ wo)
{
    const int z = blockIdx.y;
    const int idx = blockIdx.x * 256 + threadIdx.x;
    const float* src; uint32_t* dh; uint32_t* dl; int np;
    switch (z) {
        case 0: src = q;  dh = g_XAh[0]; dl = g_XAl[0]; np = MROWS * DPAIRS; break;
        case 1: src = k;  dh = g_XAh[1]; dl = g_XAl[1]; np = MROWS * DPAIRS; break;
        case 2: src = v;  dh = g_XAh[2]; dl = g_XAl[2]; np = MROWS * DPAIRS; break;
        case 3: src = wq; dh = g_Wh[0];  dl = g_Wl[0];  np = D_MODEL * DPAIRS; break;
        case 4: src = wk; dh = g_Wh[1];  dl = g_Wl[1];  np = D_MODEL * DPAIRS; break;
        case 5: src = wv; dh = g_Wh[2];  dl = g_Wl[2];  np = D_MODEL * DPAIRS; break;
        default: src = wo; dh = g_Wh[3]; dl = g_Wl[3];  np = D_MODEL * DPAIRS; break;
    }
    if (idx >= np) return;
    const float2 vv = ((const float2*)src)[idx];
    uint32_t h, l;
    split_bf16x2(vv.x, vv.y, h, l);
    dh[idx] = h; dl[idx] = l;
}

// ===========================================================================
// 3xBF16 GEMM, R15: CTA tile 128(M) x 64(N), 256 threads, 2 CTAs/SM.
//   8 warps (4m x 2n), warp 32x32 (acc = 32 regs -> fits 128-reg cap for
//   2 resident CTAs). Two independent barrier/cp_wait domains per SM fill
//   the chunk-boundary bubbles that pinned issue% at 15.6 with one CTA.
//   k-chunk 32, double-buffered, all-ldmatrix, rows 20 u32 (80 B).
// SMEM/CTA: 2 bufs x (A 2x[128][20] + B 2x[64][20]) = 61,440 B
// ===========================================================================
#define GROW   20
#define APLN   (128 * GROW)         // 2560 u32
#define BPLN   (64 * GROW)          // 1280 u32
#define GBUF   (2 * APLN + 2 * BPLN)  // 7680 u32 per buffer
#define OFF_AH 0
#define OFF_AL APLN
#define OFF_BH (2 * APLN)
#define OFF_BL (2 * APLN + BPLN)

__global__ __launch_bounds__(256, 2) void bf16_gemm(
    const float* __restrict__ bq_, const float* __restrict__ bk_,
    const float* __restrict__ bv_, float* __restrict__ outp, int mode)
{
    extern __shared__ __align__(16) uint32_t smg[];
    const uint32_t sb = smem_u32(smg);

    const uint32_t *Ah, *Al, *Bh, *Bl;
    const float* bias; float scale = 1.0f;
    uint32_t* dsth = nullptr; uint32_t* dstl = nullptr;
    if (mode == 0) {
        const int z = blockIdx.z;
        Ah = g_XAh[z]; Al = g_XAl[z]; Bh = g_Wh[z]; Bl = g_Wl[z];
        if (z == 0)      { bias = bq_; dsth = g_Qh; dstl = g_Ql; scale = 0.125f; }
        else if (z == 1) { bias = bk_; dsth = g_Kh; dstl = g_Kl; }
        else             { bias = bv_; dsth = g_Vh; dstl = g_Vl; }
    } else {
        Ah = g_Oh; Al = g_Ol; Bh = g_Wh[3]; Bl = g_Wl[3]; bias = bq_;
    }

    const int tid = threadIdx.x;
    const int wid = tid >> 5, lid = tid & 31;
    const int g = lid >> 2, tg = lid & 3;
    const int mwarp = wid & 3, nwarp = wid >> 2;     // 4m x 2n warp grid
    const int m0 = blockIdx.y * 128, n0 = blockIdx.x * 64;

    // per-chunk loader: 1536 x 16B (A: 1024, B: 512), 6 per thread
    auto load_chunk = [&](int buf, int chunk) {
        const int kcol = chunk * 16;
#pragma unroll
        for (int t = 0; t < 6; t++) {
            const int f = tid + 256 * t;
            const uint32_t* srcb;
            uint32_t dstoff;
            int r, cc;
            if (f < 1024) {                       // A planes
                const int plane = f >> 9;
                const int r2 = f & 511;
                r = r2 >> 2; cc = r2 & 3;
                srcb = (plane ? Al : Ah) + (size_t)(m0 + r) * DPAIRS;
                dstoff = (plane ? OFF_AL : OFF_AH);
            } else {                              // B planes
                const int fb = f - 1024;
                const int plane = fb >> 8;
                const int r2 = fb & 255;
                r = r2 >> 2; cc = r2 & 3;
                srcb = (plane ? Bl : Bh) + (size_t)(n0 + r) * DPAIRS;
                dstoff = (plane ? OFF_BL : OFF_BH);
            }
            const uint32_t doff = (uint32_t)(buf * GBUF + dstoff + r * GROW + cc * 4);
            cp_async16(sb + doff * 4u, srcb + kcol + cc * 4);
        }
    };

    float acc[2][4][4];
#pragma unroll
    for (int i = 0; i < 2; i++)
#pragma unroll
        for (int j = 0; j < 4; j++)
#pragma unroll
            for (int e = 0; e < 4; e++) acc[i][j][e] = 0.0f;

    load_chunk(0, 0);
    cp_commit();

    for (int c = 0; c < 16; c++) {
        const int buf = c & 1;
        if (c < 15) {
            load_chunk(buf ^ 1, c + 1);
            cp_commit();
            cp_wait<1>();
        } else {
            cp_wait<0>();
        }
        __syncthreads();

        const uint32_t abase = sb + (uint32_t)(buf * GBUF) * 4u;
#pragma unroll
        for (int ks = 0; ks < 2; ks++) {
            // A fragments: 2 m-tiles x 2 planes, ldmatrix.x4
            const uint32_t kb = (uint32_t)((lid >> 4) * 16 + ks * 32);
            uint32_t ah[2][4], al[2][4];
#pragma unroll
            for (int i = 0; i < 2; i++) {
                const uint32_t row = (uint32_t)(mwarp * 32 + i * 16 + (lid & 15));
                ldsm_x4(ah[i], abase + (OFF_AH * 4u) + row * (GROW * 4) + kb);
                ldsm_x4(al[i], abase + (OFF_AL * 4u) + row * (GROW * 4) + kb);
            }
            // B fragments: x4 over j-pairs (lanes 16-31 -> second j tile)
            uint32_t bh[4][2], bl[4][2];
            const uint32_t kbB = (uint32_t)(((lid >> 3) & 1) * 16 + ks * 32);
#pragma unroll
            for (int jp = 0; jp < 2; jp++) {
                const uint32_t row = (uint32_t)(nwarp * 32 + jp * 16 + ((lid >> 4) & 1) * 8 + (lid & 7));
                uint32_t r4[4];
                ldsm_x4(r4, abase + (OFF_BH * 4u) + row * (GROW * 4) + kbB);
                bh[jp * 2][0] = r4[0]; bh[jp * 2][1] = r4[1];
                bh[jp * 2 + 1][0] = r4[2]; bh[jp * 2 + 1][1] = r4[3];
                ldsm_x4(r4, abase + (OFF_BL * 4u) + row * (GROW * 4) + kbB);
                bl[jp * 2][0] = r4[0]; bl[jp * 2][1] = r4[1];
                bl[jp * 2 + 1][0] = r4[2]; bl[jp * 2 + 1][1] = r4[3];
            }
            // 3 passes over 8 acc tiles
#pragma unroll
            for (int i = 0; i < 2; i++)
#pragma unroll
                for (int j = 0; j < 4; j++) mma_bf16(acc[i][j], ah[i], bh[j]);
#pragma unroll
            for (int i = 0; i < 2; i++)
#pragma unroll
                for (int j = 0; j < 4; j++) mma_bf16(acc[i][j], al[i], bh[j]);
#pragma unroll
            for (int i = 0; i < 2; i++)
#pragma unroll
                for (int j = 0; j < 4; j++) mma_bf16(acc[i][j], ah[i], bl[j]);
        }
        __syncthreads();
    }

    // ---- epilogue ----
#pragma unroll
    for (int j = 0; j < 4; j++) {
        const int n = n0 + nwarp * 32 + j * 8 + 2 * tg;      // even column
        const float bv0 = __ldg(&bias[n]), bv1 = __ldg(&bias[n + 1]);
#pragma unroll
        for (int i = 0; i < 2; i++) {
            const int mA = m0 + mwarp * 32 + i * 16 + g;
            const int mB = mA + 8;
            const float v0 = (acc[i][j][0] + bv0) * scale;
            const float v1 = (acc[i][j][1] + bv1) * scale;
            const float v2 = (acc[i][j][2] + bv0) * scale;
            const float v3 = (acc[i][j][3] + bv1) * scale;
            if (mode == 0) {
                const int h = n >> 6, dkp = (n & 63) >> 1;
                const int bA = mA >> 11, sA = mA & (S_LEN - 1);
                const int bB = mB >> 11, sB = mB & (S_LEN - 1);
                uint32_t hh, ll;
                split_bf16x2(v0, v1, hh, ll);
                const size_t iA = ((size_t)(bA * NH + h) * S_LEN + sA) * PAIRS + dkp;
                dsth[iA] = hh; dstl[iA] = ll;
                split_bf16x2(v2, v3, hh, ll);
                const size_t iB = ((size_t)(bB * NH + h) * S_LEN + sB) * PAIRS + dkp;
                dsth[iB] = hh; dstl[iB] = ll;
            } else {
                *(float2*)&outp[(size_t)mA * D_MODEL + n] = make_float2(v0, v1);
                *(float2*)&outp[(size_t)mB * D_MODEL + n] = make_float2(v2, v3);
            }
        }
    }
}

// ===========================================================================
// 3xBF16 flash attention — byte-identical to the verified R12/R14 kernel.
//   512 threads, 256-row q-tile, 16 warps x 16 rows, 64-key chunks.
// SMEM total 55296 u32 = 221,184 B
// ===========================================================================
#define S_Q_H 0
#define S_Q_L 9216
#define S_P_H 18432
#define S_P_L 27648
#define S_K_H(b) (36864 + (b) * 2304)
#define S_K_L(b) (41472 + (b) * 2304)
#define S_V_H(b) (46080 + (b) * 2304)
#define S_V_L(b) (50688 + (b) * 2304)
#define NCHUNK (S_LEN / 64)
#define QTILE  256

__global__ __launch_bounds__(512, 1) void attn_mma()
{
    extern __shared__ __align__(16) uint32_t sm[];
    const uint32_t sb = smem_u32(sm);

    const int tid = threadIdx.x;
    const int wid = tid >> 5, lid = tid & 31;
    const int g = lid >> 2, tg = lid & 3;
    const int bh = blockIdx.y;
    const int q0 = blockIdx.x * QTILE;
    const int qr = wid * 16;

    const uint32_t* Qh = g_Qh + ((size_t)bh * S_LEN + q0) * PAIRS;
    const uint32_t* Ql = g_Ql + ((size_t)bh * S_LEN + q0) * PAIRS;
    const uint32_t* Kh = g_Kh + (size_t)bh * S_LEN * PAIRS;
    const uint32_t* Kl = g_Kl + (size_t)bh * S_LEN * PAIRS;
    const uint32_t* Vh = g_Vh + (size_t)bh * S_LEN * PAIRS;
    const uint32_t* Vl = g_Vl + (size_t)bh * S_LEN * PAIRS;

    auto load_kv = [&](int buf, int kt) {
        const size_t base = (size_t)kt * 64 * PAIRS;
#pragma unroll
        for (int t = 0; t < 4; t++) {
            const int f = tid + 512 * t;
            const int plane = f >> 9;
            const int rem = f & 511;
            const int r = rem >> 3, cc = rem & 7;
            const uint32_t* src;
            uint32_t dst;
            const size_t so = base + (size_t)r * PAIRS + cc * 4;
            if (plane == 0)      { src = Kh + so; dst = (uint32_t)S_K_H(buf); }
            else if (plane == 1) { src = Kl + so; dst = (uint32_t)S_K_L(buf); }
            else if (plane == 2) { src = Vh + so; dst = (uint32_t)S_V_H(buf); }
            else                 { src = Vl + so; dst = (uint32_t)S_V_L(buf); }
            cp_async16(sb + (dst + (uint32_t)(r * 36 + cc * 4)) * 4u, src);
        }
    };

    // Prologue: Q (2 planes x 256 rows x 8) + KV chunk 0
#pragma unroll
    for (int t = 0; t < 8; t++) {
        const int f = tid + 512 * t;
        const int plane = f >> 11;
        const int rem = f & 2047;
        const int r = rem >> 3, cc = rem & 7;
        const uint32_t* src = (plane ? Ql : Qh) + (size_t)r * PAIRS + cc * 4;
        const uint32_t dst = (uint32_t)(plane ? S_Q_L : S_Q_H) + (uint32_t)(r * 36 + cc * 4);
        cp_async16(sb + dst * 4u, src);
    }
    load_kv(0, 0);
    cp_commit();
    cp_wait<0>();
    __syncthreads();

    load_kv(1, 1);
    cp_commit();

    float m0 = -1e30f, m1 = -1e30f, l0 = 0.0f, l1 = 0.0f;
    float o[8][4];
#pragma unroll
    for (int nt = 0; nt < 8; nt++)
#pragma unroll
        for (int e = 0; e < 4; e++) o[nt][e] = 0.0f;

    const uint32_t qrowb = (uint32_t)(qr + (lid & 15)) * 144u + (uint32_t)((lid >> 4) * 16);

    for (int kt = 0; kt < NCHUNK; kt++) {
        const int buf = kt & 1;

        float s[8][4];
#pragma unroll
        for (int nt = 0; nt < 8; nt++)
#pragma unroll
            for (int e = 0; e < 4; e++) s[nt][e] = 0.0f;

        const uint32_t khb = sb + (uint32_t)S_K_H(buf) * 4u;
        const uint32_t klb = sb + (uint32_t)S_K_L(buf) * 4u;
        const uint32_t kroff = (uint32_t)(((lid >> 4) & 1) * 8 + (lid & 7)) * 144u
                             + (uint32_t)(((lid >> 3) & 1) * 16);
#pragma unroll
        for (int kc = 0; kc < 4; kc++) {
            uint32_t aH[4], aL[4];
            ldsm_x4(aH, sb + (uint32_t)S_Q_H * 4u + qrowb + kc * 32);
            ldsm_x4(aL, sb + (uint32_t)S_Q_L * 4u + qrowb + kc * 32);
#pragma unroll
            for (int ntp = 0; ntp < 4; ntp++) {
                const uint32_t ro = (uint32_t)(ntp * 16) * 144u + kroff + kc * 32;
                uint32_t rH[4], rL[4];
                ldsm_x4(rH, khb + ro);
                ldsm_x4(rL, klb + ro);
                mma_bf16(s[ntp * 2],     aH, &rH[0]);
                mma_bf16(s[ntp * 2],     aL, &rH[0]);
                mma_bf16(s[ntp * 2],     aH, &rL[0]);
                mma_bf16(s[ntp * 2 + 1], aH, &rH[2]);
                mma_bf16(s[ntp * 2 + 1], aL, &rH[2]);
                mma_bf16(s[ntp * 2 + 1], aH, &rL[2]);
            }
        }

        // ---- online softmax ----
        {
            float mx0 = -1e30f, mx1 = -1e30f;
#pragma unroll
            for (int nt = 0; nt < 8; nt++) {
                mx0 = fmaxf(mx0, fmaxf(s[nt][0], s[nt][1]));
                mx1 = fmaxf(mx1, fmaxf(s[nt][2], s[nt][3]));
            }
            mx0 = fmaxf(mx0, __shfl_xor_sync(0xffffffffu, mx0, 1));
            mx0 = fmaxf(mx0, __shfl_xor_sync(0xffffffffu, mx0, 2));
            mx1 = fmaxf(mx1, __shfl_xor_sync(0xffffffffu, mx1, 1));
            mx1 = fmaxf(mx1, __shfl_xor_sync(0xffffffffu, mx1, 2));
            const float nm0 = fmaxf(m0, mx0), nm1 = fmaxf(m1, mx1);
            const float al0 = __expf(m0 - nm0), al1 = __expf(m1 - nm1);
            m0 = nm0; m1 = nm1;
            float sum0 = 0.0f, sum1 = 0.0f;
#pragma unroll
            for (int nt = 0; nt < 8; nt++) {
                s[nt][0] = __expf(s[nt][0] - nm0);
                s[nt][1] = __expf(s[nt][1] - nm0);
                s[nt][2] = __expf(s[nt][2] - nm1);
                s[nt][3] = __expf(s[nt][3] - nm1);
                sum0 += s[nt][0] + s[nt][1];
                sum1 += s[nt][2] + s[nt][3];
            }
            sum0 += __shfl_xor_sync(0xffffffffu, sum0, 1);
            sum0 += __shfl_xor_sync(0xffffffffu, sum0, 2);
            sum1 += __shfl_xor_sync(0xffffffffu, sum1, 1);
            sum1 += __shfl_xor_sync(0xffffffffu, sum1, 2);
            l0 = l0 * al0 + sum0;
            l1 = l1 * al1 + sum1;
#pragma unroll
            for (int nt = 0; nt < 8; nt++) {
                o[nt][0] *= al0; o[nt][1] *= al0;
                o[nt][2] *= al1; o[nt][3] *= al1;
            }
        }

        // ---- stage P (hi/lo), warp-local rows ----
#pragma unroll
        for (int nt = 0; nt < 8; nt++) {
            uint32_t h0, lo0, h1, lo1;
            split_bf16x2(s[nt][0], s[nt][1], h0, lo0);
            split_bf16x2(s[nt][2], s[nt][3], h1, lo1);
            const int kp = nt * 4 + tg;
            sm[S_P_H + (qr + g) * 36 + kp]     = h0;
            sm[S_P_L + (qr + g) * 36 + kp]     = lo0;
            sm[S_P_H + (qr + g + 8) * 36 + kp] = h1;
            sm[S_P_L + (qr + g + 8) * 36 + kp] = lo1;
        }
        __syncwarp();

        // ---- O += P V ----
        const uint32_t prowb = (uint32_t)(qr + (lid & 15)) * 144u + (uint32_t)((lid >> 4) * 16);
        const uint32_t vb_h = sb + (uint32_t)S_V_H(buf) * 4u;
        const uint32_t vb_l = sb + (uint32_t)S_V_L(buf) * 4u;
#pragma unroll
        for (int kc = 0; kc < 4; kc++) {
            uint32_t paH[4], paL[4];
            ldsm_x4(paH, sb + (uint32_t)S_P_H * 4u + prowb + kc * 32);
            ldsm_x4(paL, sb + (uint32_t)S_P_L * 4u + prowb + kc * 32);
            const uint32_t vrow = (uint32_t)(kc * 16 + (lid & 15)) * 144u
                                + (uint32_t)((lid >> 4) * 16);
#pragma unroll
            for (int ntp = 0; ntp < 4; ntp++) {
                uint32_t rH[4], rL[4];
                ldsm_x4_trans(rH, vb_h + vrow + ntp * 32);
                ldsm_x4_trans(rL, vb_l + vrow + ntp * 32);
                mma_bf16(o[ntp * 2],     paH, &rH[0]);
                mma_bf16(o[ntp * 2],     paL, &rH[0]);
                mma_bf16(o[ntp * 2],     paH, &rL[0]);
                mma_bf16(o[ntp * 2 + 1], paH, &rH[2]);
                mma_bf16(o[ntp * 2 + 1], paL, &rH[2]);
                mma_bf16(o[ntp * 2 + 1], paH, &rL[2]);
            }
        }

        // ---- pipeline tail ----
        if (kt + 1 < NCHUNK) {
            cp_wait<0>();
            __syncthreads();
            if (kt + 2 < NCHUNK) {
                load_kv(buf, kt + 2);
                cp_commit();
            }
        }
    }

    // ---- normalize + write pre-split merged-head O planes ----
    const int b = bh >> 3, h = bh & 7;
    const float inv0 = 1.0f / l0, inv1 = 1.0f / l1;
    const int row0 = q0 + qr + g, row1 = row0 + 8;
#pragma unroll
    for (int nt = 0; nt < 8; nt++) {
        const int cp = h * 32 + nt * 4 + tg;
        uint32_t hh, ll;
        split_bf16x2(o[nt][0] * inv0, o[nt][1] * inv0, hh, ll);
        g_Oh[(size_t)(b * S_LEN + row0) * DPAIRS + cp] = hh;
        g_Ol[(size_t)(b * S_LEN + row0) * DPAIRS + cp] = ll;
        split_bf16x2(o[nt][2] * inv1, o[nt][3] * inv1, hh, ll);
        g_Oh[(size_t)(b * S_LEN + row1) * DPAIRS + cp] = hh;
        g_Ol[(size_t)(b * S_LEN + row1) * DPAIRS + cp] = ll;
    }
}

// ---------------------------------------------------------------------------
extern "C" void kernel_launch(void* const* d_in, const int* in_sizes, int n_in,
                              void* d_out, int out_size)
{
    const float* q   = (const float*)d_in[0];
    const float* v   = (const float*)d_in[1];
    const float* k   = (const float*)d_in[2];
    const float* w_q = (const float*)d_in[3];
    const float* b_q = (const float*)d_in[4];
    const float* w_k = (const float*)d_in[5];
    const float* b_k = (const float*)d_in[6];
    const float* w_v = (const float*)d_in[7];
    const float* b_v = (const float*)d_in[8];
    const float* w_o = (const float*)d_in[9];
    const float* b_o = (const float*)d_in[10];
    float* out = (float*)d_out;

    const int gemm_smem = 2 * GBUF * 4;   // 61,440 B per CTA (2 CTAs/SM)
    const int attn_smem = 55296 * 4;      // 221,184 B
    cudaFuncSetAttribute(bf16_gemm, cudaFuncAttributeMaxDynamicSharedMemorySize,
                         gemm_smem);
    cudaFuncSetAttribute(attn_mma, cudaFuncAttributeMaxDynamicSharedMemorySize,
                         attn_smem);

    // 0) Pre-split all inputs to bf16 hi/lo planes
    split_inputs<<<dim3(MROWS * DPAIRS / 256, 7), 256>>>(q, k, v, w_q, w_k, w_v, w_o);
    // 1) Q/K/V projections (3xBF16, 128x64 tiles, 2 CTAs/SM)
    bf16_gemm<<<dim3(D_MODEL / 64, MROWS / 128, 3), 256, gemm_smem>>>(
        b_q, b_k, b_v, nullptr, 0);
    // 2) Flash attention (unchanged R14)
    attn_mma<<<dim3(S_LEN / QTILE, BHCNT), 512, attn_smem>>>();
    // 3) Output projection (3xBF16, 128x64 tiles, 2 CTAs/SM) -> fp32 d_out
    bf16_gemm<<<dim3(D_MODEL / 64, MROWS / 128, 1), 256, gemm_smem>>>(
        b_o, nullptr, nullptr, out, 1);
}

// round 16
// speedup vs baseline: 1.5836x; 1.5836x over previous
#include <cuda_runtime.h>
#include <cuda_bf16.h>
#include <cstdint>

// Problem constants
#define D_MODEL 512
#define S_LEN   2048
#define NB      2
#define NH      8
#define DK      64
#define MROWS   (NB * S_LEN)    // 4096
#define BHCNT   (NB * NH)       // 16
#define PAIRS   (DK / 2)        // 32 u32 per head row
#define DPAIRS  (D_MODEL / 2)   // 256 u32 per full row

// --------------------------------------------------------------------------
// Pre-split bf16 hi/lo planes (pair-packed u32 = [bf16 even | bf16 odd])
// --------------------------------------------------------------------------
__device__ uint32_t g_XAh[3][MROWS * DPAIRS];   // q/k/v activations
__device__ uint32_t g_XAl[3][MROWS * DPAIRS];
__device__ uint32_t g_Wh[4][D_MODEL * DPAIRS];  // w_q w_k w_v w_o
__device__ uint32_t g_Wl[4][D_MODEL * DPAIRS];
__device__ uint32_t g_Oh[MROWS * DPAIRS];       // attention output planes
__device__ uint32_t g_Ol[MROWS * DPAIRS];
// head-split projection outputs
__device__ uint32_t g_Qh[BHCNT * S_LEN * PAIRS];
__device__ uint32_t g_Ql[BHCNT * S_LEN * PAIRS];
__device__ uint32_t g_Kh[BHCNT * S_LEN * PAIRS];
__device__ uint32_t g_Kl[BHCNT * S_LEN * PAIRS];
__device__ uint32_t g_Vh[BHCNT * S_LEN * PAIRS];
__device__ uint32_t g_Vl[BHCNT * S_LEN * PAIRS];

// ===========================================================================
// Helpers (plain sm_75/80 PTX, no 'a'-features)
// ===========================================================================
__device__ __forceinline__ void mma_bf16(float* d, const uint32_t* a, const uint32_t* b)
{
    asm volatile(
        "mma.sync.aligned.m16n8k16.row.col.f32.bf16.bf16.f32 "
        "{%0,%1,%2,%3}, {%4,%5,%6,%7}, {%8,%9}, {%0,%1,%2,%3};"
        : "+f"(d[0]), "+f"(d[1]), "+f"(d[2]), "+f"(d[3])
        : "r"(a[0]), "r"(a[1]), "r"(a[2]), "r"(a[3]), "r"(b[0]), "r"(b[1]));
}

__device__ __forceinline__ void ldsm_x4(uint32_t* r, uint32_t addr)
{
    asm volatile("ldmatrix.sync.aligned.m8n8.x4.shared.b16 {%0,%1,%2,%3}, [%4];"
                 : "=r"(r[0]), "=r"(r[1]), "=r"(r[2]), "=r"(r[3]) : "r"(addr));
}
__device__ __forceinline__ void ldsm_x4_trans(uint32_t* r, uint32_t addr)
{
    asm volatile("ldmatrix.sync.aligned.m8n8.x4.trans.shared.b16 {%0,%1,%2,%3}, [%4];"
                 : "=r"(r[0]), "=r"(r[1]), "=r"(r[2]), "=r"(r[3]) : "r"(addr));
}

__device__ __forceinline__ uint32_t smem_u32(const void* p) {
    uint32_t addr;
    asm("{ .reg .u64 tmp; cvta.to.shared.u64 tmp, %1; cvt.u32.u64 %0, tmp; }"
        : "=r"(addr) : "l"(p));
    return addr;
}

__device__ __forceinline__ void cp_async16(uint32_t dst, const void* src) {
    asm volatile("cp.async.cg.shared.global [%0], [%1], 16;" :: "r"(dst), "l"(src));
}
__device__ __forceinline__ void cp_commit() {
    asm volatile("cp.async.commit_group;" ::: "memory");
}
template <int N>
__device__ __forceinline__ void cp_wait() {
    asm volatile("cp.async.wait_group %0;" :: "n"(N) : "memory");
}

__device__ __forceinline__ void split_bf16x2(float x, float y, uint32_t& h, uint32_t& l)
{
    __nv_bfloat162 hb = __floats2bfloat162_rn(x, y);
    h = *reinterpret_cast<uint32_t*>(&hb);
    float rx = x - __bfloat162float(hb.x);
    float ry = y - __bfloat162float(hb.y);
    __nv_bfloat162 lb = __floats2bfloat162_rn(rx, ry);
    l = *reinterpret_cast<uint32_t*>(&lb);
}

// ===========================================================================
// Pre-split pass: fp32 -> bf16 hi/lo planes. One pair per thread.
// ===========================================================================
__global__ __launch_bounds__(256) void split_inputs(
    const float* __restrict__ q, const float* __restrict__ k,
    const float* __restrict__ v,
    const float* __restrict__ wq, const float* __restrict__ wk,
    const float* __restrict__ wv, const float* __restrict__ wo)
{
    const int z = blockIdx.y;
    const int idx = blockIdx.x * 256 + threadIdx.x;
    const float* src; uint32_t* dh; uint32_t* dl; int np;
    switch (z) {
        case 0: src = q;  dh = g_XAh[0]; dl = g_XAl[0]; np = MROWS * DPAIRS; break;
        case 1: src = k;  dh = g_XAh[1]; dl = g_XAl[1]; np = MROWS * DPAIRS; break;
        case 2: src = v;  dh = g_XAh[2]; dl = g_XAl[2]; np = MROWS * DPAIRS; break;
        case 3: src = wq; dh = g_Wh[0];  dl = g_Wl[0];  np = D_MODEL * DPAIRS; break;
        case 4: src = wk; dh = g_Wh[1];  dl = g_Wl[1];  np = D_MODEL * DPAIRS; break;
        case 5: src = wv; dh = g_Wh[2];  dl = g_Wl[2];  np = D_MODEL * DPAIRS; break;
        default: src = wo; dh = g_Wh[3]; dl = g_Wl[3];  np = D_MODEL * DPAIRS; break;
    }
    if (idx >= np) return;
    const float2 vv = ((const float2*)src)[idx];
    uint32_t h, l;
    split_bf16x2(vv.x, vv.y, h, l);
    dh[idx] = h; dl[idx] = l;
}

// ===========================================================================
// 3xBF16 GEMM — byte-identical to the verified R14 kernel (tied-best).
//   512 threads, CTA 128x128, 16 warps (4m x 4n), warp 32x32, k-chunk 32.
// SMEM: 2 bufs x 4 planes x [128][20] u32 = 81,920 B
// ===========================================================================
#define GROW  20
#define GPLN  (128 * GROW)          // 2560 u32 per plane
#define GBUF  (4 * GPLN)            // 10240 u32 per buffer

__global__ __launch_bounds__(512, 1) void bf16_gemm(
    const float* __restrict__ bq_, const float* __restrict__ bk_,
    const float* __restrict__ bv_, float* __restrict__ outp, int mode)
{
    extern __shared__ __align__(16) uint32_t smg[];
    const uint32_t sb = smem_u32(smg);

    const uint32_t *Ah, *Al, *Bh, *Bl;
    const float* bias; float scale = 1.0f;
    uint32_t* dsth = nullptr; uint32_t* dstl = nullptr;
    if (mode == 0) {
        const int z = blockIdx.z;
        Ah = g_XAh[z]; Al = g_XAl[z]; Bh = g_Wh[z]; Bl = g_Wl[z];
        if (z == 0)      { bias = bq_; dsth = g_Qh; dstl = g_Ql; scale = 0.125f; }
        else if (z == 1) { bias = bk_; dsth = g_Kh; dstl = g_Kl; }
        else             { bias = bv_; dsth = g_Vh; dstl = g_Vl; }
    } else {
        Ah = g_Oh; Al = g_Ol; Bh = g_Wh[3]; Bl = g_Wl[3]; bias = bq_;
    }

    const int tid = threadIdx.x;
    const int wid = tid >> 5, lid = tid & 31;
    const int g = lid >> 2, tg = lid & 3;
    const int mwarp = wid & 3, nwarp = wid >> 2;     // 4 x 4 warp grid
    const int m0 = blockIdx.y * 128, n0 = blockIdx.x * 128;

    auto load_chunk = [&](int buf, int chunk) {
        const int kcol = chunk * 16;
#pragma unroll
        for (int t = 0; t < 4; t++) {
            const int f = tid + 512 * t;
            const int isB = f >> 10;
            const int rem = f & 1023;
            const int plane = rem >> 9;
            const int r2 = rem & 511;
            const int r = r2 >> 2, cc = r2 & 3;
            const uint32_t* base = isB ? (plane ? Bl : Bh) : (plane ? Al : Ah);
            const uint32_t* src = base + (size_t)((isB ? n0 : m0) + r) * DPAIRS + kcol + cc * 4;
            const uint32_t doff = (uint32_t)(buf * GBUF + (isB * 2 + plane) * GPLN + r * GROW + cc * 4);
            cp_async16(sb + doff * 4u, src);
        }
    };

    float acc[2][4][4];
#pragma unroll
    for (int i = 0; i < 2; i++)
#pragma unroll
        for (int j = 0; j < 4; j++)
#pragma unroll
            for (int e = 0; e < 4; e++) acc[i][j][e] = 0.0f;

    load_chunk(0, 0);
    cp_commit();

    for (int c = 0; c < 16; c++) {
        const int buf = c & 1;
        if (c < 15) {
            load_chunk(buf ^ 1, c + 1);
            cp_commit();
            cp_wait<1>();
        } else {
            cp_wait<0>();
        }
        __syncthreads();

        const uint32_t abase = sb + (uint32_t)(buf * GBUF) * 4u;
#pragma unroll
        for (int ks = 0; ks < 2; ks++) {
            const uint32_t kb = (uint32_t)((lid >> 4) * 16 + ks * 32);
            uint32_t ah[2][4], al[2][4];
#pragma unroll
            for (int i = 0; i < 2; i++) {
                const uint32_t row = (uint32_t)(mwarp * 32 + i * 16 + (lid & 15));
                ldsm_x4(ah[i], abase + row * (GROW * 4) + kb);
                ldsm_x4(al[i], abase + GPLN * 4 + row * (GROW * 4) + kb);
            }
            uint32_t bh[4][2], bl[4][2];
            const uint32_t kbB = (uint32_t)(((lid >> 3) & 1) * 16 + ks * 32);
#pragma unroll
            for (int jp = 0; jp < 2; jp++) {
                const uint32_t row = (uint32_t)(nwarp * 32 + jp * 16 + ((lid >> 4) & 1) * 8 + (lid & 7));
                uint32_t r4[4];
                ldsm_x4(r4, abase + 2 * GPLN * 4 + row * (GROW * 4) + kbB);
                bh[jp * 2][0] = r4[0]; bh[jp * 2][1] = r4[1];
                bh[jp * 2 + 1][0] = r4[2]; bh[jp * 2 + 1][1] = r4[3];
                ldsm_x4(r4, abase + 3 * GPLN * 4 + row * (GROW * 4) + kbB);
                bl[jp * 2][0] = r4[0]; bl[jp * 2][1] = r4[1];
                bl[jp * 2 + 1][0] = r4[2]; bl[jp * 2 + 1][1] = r4[3];
            }
#pragma unroll
            for (int i = 0; i < 2; i++)
#pragma unroll
                for (int j = 0; j < 4; j++) mma_bf16(acc[i][j], ah[i], bh[j]);
#pragma unroll
            for (int i = 0; i < 2; i++)
#pragma unroll
                for (int j = 0; j < 4; j++) mma_bf16(acc[i][j], al[i], bh[j]);
#pragma unroll
            for (int i = 0; i < 2; i++)
#pragma unroll
                for (int j = 0; j < 4; j++) mma_bf16(acc[i][j], ah[i], bl[j]);
        }
        __syncthreads();
    }

    // ---- epilogue ----
#pragma unroll
    for (int j = 0; j < 4; j++) {
        const int n = n0 + nwarp * 32 + j * 8 + 2 * tg;      // even column
        const float bv0 = __ldg(&bias[n]), bv1 = __ldg(&bias[n + 1]);
#pragma unroll
        for (int i = 0; i < 2; i++) {
            const int mA = m0 + mwarp * 32 + i * 16 + g;
            const int mB = mA + 8;
            const float v0 = (acc[i][j][0] + bv0) * scale;
            const float v1 = (acc[i][j][1] + bv1) * scale;
            const float v2 = (acc[i][j][2] + bv0) * scale;
            const float v3 = (acc[i][j][3] + bv1) * scale;
            if (mode == 0) {
                const int h = n >> 6, dkp = (n & 63) >> 1;
                const int bA = mA >> 11, sA = mA & (S_LEN - 1);
                const int bB = mB >> 11, sB = mB & (S_LEN - 1);
                uint32_t hh, ll;
                split_bf16x2(v0, v1, hh, ll);
                const size_t iA = ((size_t)(bA * NH + h) * S_LEN + sA) * PAIRS + dkp;
                dsth[iA] = hh; dstl[iA] = ll;
                split_bf16x2(v2, v3, hh, ll);
                const size_t iB = ((size_t)(bB * NH + h) * S_LEN + sB) * PAIRS + dkp;
                dsth[iB] = hh; dstl[iB] = ll;
            } else {
                *(float2*)&outp[(size_t)mA * D_MODEL + n] = make_float2(v0, v1);
                *(float2*)&outp[(size_t)mB * D_MODEL + n] = make_float2(v2, v3);
            }
        }
    }
}

// ===========================================================================
// 3xBF16 flash attention, R16: DIRECT P-fragment conversion (no smem P).
//   The m16n8 score accumulator layout (rows g/g+8, cols 2tg,2tg+1 of tile
//   nt) maps exactly onto m16n8k16 A-operand fragments: for PV k-chunk kc,
//   a0..a3 = pack(s[2kc][0..1]), pack(s[2kc][2..3]), pack(s[2kc+1][0..1]),
//   pack(s[2kc+1][2..3]). Removes per-warp-per-chunk: 32 STS + 8 ldmatrix
//   + __syncwarp (~20% of attention LDSM traffic). Everything else (online
//   softmax, K/V pipeline, V ldmatrix.trans) identical to verified R14.
//
// SMEM (u32 offsets, rows 36 u32 = 144 B):
//   Q_H 0 [256][36]  Q_L 9216
//   K_H(b) 18432+b*2304  K_L(b) 23040+b*2304
//   V_H(b) 27648+b*2304  V_L(b) 32256+b*2304
// Total 36864 u32 = 147,456 B
// ===========================================================================
#define S_Q_H 0
#define S_Q_L 9216
#define S_K_H(b) (18432 + (b) * 2304)
#define S_K_L(b) (23040 + (b) * 2304)
#define S_V_H(b) (27648 + (b) * 2304)
#define S_V_L(b) (32256 + (b) * 2304)
#define NCHUNK (S_LEN / 64)
#define QTILE  256

__global__ __launch_bounds__(512, 1) void attn_mma()
{
    extern __shared__ __align__(16) uint32_t sm[];
    const uint32_t sb = smem_u32(sm);

    const int tid = threadIdx.x;
    const int wid = tid >> 5, lid = tid & 31;
    const int bh = blockIdx.y;
    const int q0 = blockIdx.x * QTILE;
    const int qr = wid * 16;
    const int g = lid >> 2, tg = lid & 3;

    const uint32_t* Qh = g_Qh + ((size_t)bh * S_LEN + q0) * PAIRS;
    const uint32_t* Ql = g_Ql + ((size_t)bh * S_LEN + q0) * PAIRS;
    const uint32_t* Kh = g_Kh + (size_t)bh * S_LEN * PAIRS;
    const uint32_t* Kl = g_Kl + (size_t)bh * S_LEN * PAIRS;
    const uint32_t* Vh = g_Vh + (size_t)bh * S_LEN * PAIRS;
    const uint32_t* Vl = g_Vl + (size_t)bh * S_LEN * PAIRS;

    auto load_kv = [&](int buf, int kt) {
        const size_t base = (size_t)kt * 64 * PAIRS;
#pragma unroll
        for (int t = 0; t < 4; t++) {
            const int f = tid + 512 * t;
            const int plane = f >> 9;
            const int rem = f & 511;
            const int r = rem >> 3, cc = rem & 7;
            const uint32_t* src;
            uint32_t dst;
            const size_t so = base + (size_t)r * PAIRS + cc * 4;
            if (plane == 0)      { src = Kh + so; dst = (uint32_t)S_K_H(buf); }
            else if (plane == 1) { src = Kl + so; dst = (uint32_t)S_K_L(buf); }
            else if (plane == 2) { src = Vh + so; dst = (uint32_t)S_V_H(buf); }
            else                 { src = Vl + so; dst = (uint32_t)S_V_L(buf); }
            cp_async16(sb + (dst + (uint32_t)(r * 36 + cc * 4)) * 4u, src);
        }
    };

    // Prologue: Q (2 planes x 256 rows x 8) + KV chunk 0
#pragma unroll
    for (int t = 0; t < 8; t++) {
        const int f = tid + 512 * t;
        const int plane = f >> 11;
        const int rem = f & 2047;
        const int r = rem >> 3, cc = rem & 7;
        const uint32_t* src = (plane ? Ql : Qh) + (size_t)r * PAIRS + cc * 4;
        const uint32_t dst = (uint32_t)(plane ? S_Q_L : S_Q_H) + (uint32_t)(r * 36 + cc * 4);
        cp_async16(sb + dst * 4u, src);
    }
    load_kv(0, 0);
    cp_commit();
    cp_wait<0>();
    __syncthreads();

    load_kv(1, 1);
    cp_commit();

    float m0 = -1e30f, m1 = -1e30f, l0 = 0.0f, l1 = 0.0f;
    float o[8][4];
#pragma unroll
    for (int nt = 0; nt < 8; nt++)
#pragma unroll
        for (int e = 0; e < 4; e++) o[nt][e] = 0.0f;

    const uint32_t qrowb = (uint32_t)(qr + (lid & 15)) * 144u + (uint32_t)((lid >> 4) * 16);

    for (int kt = 0; kt < NCHUNK; kt++) {
        const int buf = kt & 1;

        // ---- S = Q K^T ----
        float s[8][4];
#pragma unroll
        for (int nt = 0; nt < 8; nt++)
#pragma unroll
            for (int e = 0; e < 4; e++) s[nt][e] = 0.0f;

        const uint32_t khb = sb + (uint32_t)S_K_H(buf) * 4u;
        const uint32_t klb = sb + (uint32_t)S_K_L(buf) * 4u;
        const uint32_t kroff = (uint32_t)(((lid >> 4) & 1) * 8 + (lid & 7)) * 144u
                             + (uint32_t)(((lid >> 3) & 1) * 16);
#pragma unroll
        for (int kc = 0; kc < 4; kc++) {
            uint32_t aH[4], aL[4];
            ldsm_x4(aH, sb + (uint32_t)S_Q_H * 4u + qrowb + kc * 32);
            ldsm_x4(aL, sb + (uint32_t)S_Q_L * 4u + qrowb + kc * 32);
#pragma unroll
            for (int ntp = 0; ntp < 4; ntp++) {
                const uint32_t ro = (uint32_t)(ntp * 16) * 144u + kroff + kc * 32;
                uint32_t rH[4], rL[4];
                ldsm_x4(rH, khb + ro);
                ldsm_x4(rL, klb + ro);
                mma_bf16(s[ntp * 2],     aH, &rH[0]);
                mma_bf16(s[ntp * 2],     aL, &rH[0]);
                mma_bf16(s[ntp * 2],     aH, &rL[0]);
                mma_bf16(s[ntp * 2 + 1], aH, &rH[2]);
                mma_bf16(s[ntp * 2 + 1], aL, &rH[2]);
                mma_bf16(s[ntp * 2 + 1], aH, &rL[2]);
            }
        }

        // ---- online softmax (unchanged) ----
        {
            float mx0 = -1e30f, mx1 = -1e30f;
#pragma unroll
            for (int nt = 0; nt < 8; nt++) {
                mx0 = fmaxf(mx0, fmaxf(s[nt][0], s[nt][1]));
                mx1 = fmaxf(mx1, fmaxf(s[nt][2], s[nt][3]));
            }
            mx0 = fmaxf(mx0, __shfl_xor_sync(0xffffffffu, mx0, 1));
            mx0 = fmaxf(mx0, __shfl_xor_sync(0xffffffffu, mx0, 2));
            mx1 = fmaxf(mx1, __shfl_xor_sync(0xffffffffu, mx1, 1));
            mx1 = fmaxf(mx1, __shfl_xor_sync(0xffffffffu, mx1, 2));
            const float nm0 = fmaxf(m0, mx0), nm1 = fmaxf(m1, mx1);
            const float al0 = __expf(m0 - nm0), al1 = __expf(m1 - nm1);
            m0 = nm0; m1 = nm1;
            float sum0 = 0.0f, sum1 = 0.0f;
#pragma unroll
            for (int nt = 0; nt < 8; nt++) {
                s[nt][0] = __expf(s[nt][0] - nm0);
                s[nt][1] = __expf(s[nt][1] - nm0);
                s[nt][2] = __expf(s[nt][2] - nm1);
                s[nt][3] = __expf(s[nt][3] - nm1);
                sum0 += s[nt][0] + s[nt][1];
                sum1 += s[nt][2] + s[nt][3];
            }
            sum0 += __shfl_xor_sync(0xffffffffu, sum0, 1);
            sum0 += __shfl_xor_sync(0xffffffffu, sum0, 2);
            sum1 += __shfl_xor_sync(0xffffffffu, sum1, 1);
            sum1 += __shfl_xor_sync(0xffffffffu, sum1, 2);
            l0 = l0 * al0 + sum0;
            l1 = l1 * al1 + sum1;
#pragma unroll
            for (int nt = 0; nt < 8; nt++) {
                o[nt][0] *= al0; o[nt][1] *= al0;
                o[nt][2] *= al1; o[nt][3] *= al1;
            }
        }

        // ---- DIRECT P-fragment conversion (registers only, no smem) ----
        uint32_t pH[8][2], pL[8][2];
#pragma unroll
        for (int nt = 0; nt < 8; nt++) {
            split_bf16x2(s[nt][0], s[nt][1], pH[nt][0], pL[nt][0]);
            split_bf16x2(s[nt][2], s[nt][3], pH[nt][1], pL[nt][1]);
        }

        // ---- O += P V (A-frags direct from registers; V ldmatrix.trans) ----
        const uint32_t vb_h = sb + (uint32_t)S_V_H(buf) * 4u;
        const uint32_t vb_l = sb + (uint32_t)S_V_L(buf) * 4u;
#pragma unroll
        for (int kc = 0; kc < 4; kc++) {
            uint32_t aH[4], aL[4];
            aH[0] = pH[2 * kc][0];     aL[0] = pL[2 * kc][0];
            aH[1] = pH[2 * kc][1];     aL[1] = pL[2 * kc][1];
            aH[2] = pH[2 * kc + 1][0]; aL[2] = pL[2 * kc + 1][0];
            aH[3] = pH[2 * kc + 1][1]; aL[3] = pL[2 * kc + 1][1];
            const uint32_t vrow = (uint32_t)(kc * 16 + (lid & 15)) * 144u
                                + (uint32_t)((lid >> 4) * 16);
#pragma unroll
            for (int ntp = 0; ntp < 4; ntp++) {
                uint32_t rH[4], rL[4];
                ldsm_x4_trans(rH, vb_h + vrow + ntp * 32);
                ldsm_x4_trans(rL, vb_l + vrow + ntp * 32);
                mma_bf16(o[ntp * 2],     aH, &rH[0]);
                mma_bf16(o[ntp * 2],     aL, &rH[0]);
                mma_bf16(o[ntp * 2],     aH, &rL[0]);
                mma_bf16(o[ntp * 2 + 1], aH, &rH[2]);
                mma_bf16(o[ntp * 2 + 1], aL, &rH[2]);
                mma_bf16(o[ntp * 2 + 1], aH, &rL[2]);
            }
        }

        // ---- pipeline tail ----
        if (kt + 1 < NCHUNK) {
            cp_wait<0>();
            __syncthreads();
            if (kt + 2 < NCHUNK) {
                load_kv(buf, kt + 2);
                cp_commit();
            }
        }
    }

    // ---- normalize + write pre-split merged-head O planes ----
    const int b = bh >> 3, h = bh & 7;
    const float inv0 = 1.0f / l0, inv1 = 1.0f / l1;
    const int row0 = q0 + qr + g, row1 = row0 + 8;
#pragma unroll
    for (int nt = 0; nt < 8; nt++) {
        const int cp = h * 32 + nt * 4 + tg;
        uint32_t hh, ll;
        split_bf16x2(o[nt][0] * inv0, o[nt][1] * inv0, hh, ll);
        g_Oh[(size_t)(b * S_LEN + row0) * DPAIRS + cp] = hh;
        g_Ol[(size_t)(b * S_LEN + row0) * DPAIRS + cp] = ll;
        split_bf16x2(o[nt][2] * inv1, o[nt][3] * inv1, hh, ll);
        g_Oh[(size_t)(b * S_LEN + row1) * DPAIRS + cp] = hh;
        g_Ol[(size_t)(b * S_LEN + row1) * DPAIRS + cp] = ll;
    }
}

// ---------------------------------------------------------------------------
extern "C" void kernel_launch(void* const* d_in, const int* in_sizes, int n_in,
                              void* d_out, int out_size)
{
    const float* q   = (const float*)d_in[0];
    const float* v   = (const float*)d_in[1];
    const float* k   = (const float*)d_in[2];
    const float* w_q = (const float*)d_in[3];
    const float* b_q = (const float*)d_in[4];
    const float* w_k = (const float*)d_in[5];
    const float* b_k = (const float*)d_in[6];
    const float* w_v = (const float*)d_in[7];
    const float* b_v = (const float*)d_in[8];
    const float* w_o = (const float*)d_in[9];
    const float* b_o = (const float*)d_in[10];
    float* out = (float*)d_out;

    const int gemm_smem = 2 * GBUF * 4;   // 81,920 B
    const int attn_smem = 36864 * 4;      // 147,456 B
    cudaFuncSetAttribute(bf16_gemm, cudaFuncAttributeMaxDynamicSharedMemorySize,
                         gemm_smem);
    cudaFuncSetAttribute(attn_mma, cudaFuncAttributeMaxDynamicSharedMemorySize,
                         attn_smem);

    // 0) Pre-split all inputs to bf16 hi/lo planes
    split_inputs<<<dim3(MROWS * DPAIRS / 256, 7), 256>>>(q, k, v, w_q, w_k, w_v, w_o);
    // 1) Q/K/V projections (R14 GEMM, unchanged)
    bf16_gemm<<<dim3(D_MODEL / 128, MROWS / 128, 3), 512, gemm_smem>>>(
        b_q, b_k, b_v, nullptr, 0);
    // 2) Flash attention (direct P-fragments, no smem staging)
    attn_mma<<<dim3(S_LEN / QTILE, BHCNT), 512, attn_smem>>>();
    // 3) Output projection (R14 GEMM, unchanged)
    bf16_gemm<<<dim3(D_MODEL / 128, MROWS / 128, 1), 512, gemm_smem>>>(
        b_o, nullptr, nullptr, out, 1);
}